// round 14
// baseline (speedup 1.0000x reference)
#include <cuda_runtime.h>
#include <cuda_bf16.h>
#include <cstdint>

// ---------------------------------------------------------------------------
// Problem constants
// ---------------------------------------------------------------------------
#define QN 16384      // B*N queries
#define DD 256        // dim
#define KK 8192       // codebook size
#define TM 64         // queries per block (small => 256 blocks, 2 per SM)
#define TN 128        // codes per tile
#define NTILES (KK / TN)          // 64
#define NCHUNKS (NTILES * 2)      // 128 k-half chunks
#define NTHREADS 256
#define RESCORE_T 2.5f
#define INFKEY 0xFF800000FFFFFFFFull

// smem layout (bytes): A 32K | B ring 2x32K = 96KB  (2 blocks/SM)
#define SM_A 0
#define SM_BRING 32768
#define SM_TOTAL 98304
#define SM_SCR SM_BRING           // merge scratch reuses B ring after loop
#define SM_WIN (SM_SCR + 4096)    // 64 winner indices after scratch

typedef unsigned long long ull;

// ---------------------------------------------------------------------------
// device scratch (static: no allocations allowed)
// ---------------------------------------------------------------------------
__device__ __nv_bfloat16 g_cb_hi[KK * DD];
__device__ float g_c2[KK];

// ---------------------------------------------------------------------------
// PTX helpers (sm_80-baseline: legal on plain sm_103 target)
// ---------------------------------------------------------------------------
__device__ __forceinline__ unsigned smem_u32(const void* p) {
    unsigned a;
    asm("{ .reg .u64 t; cvta.to.shared.u64 t, %1; cvt.u32.u64 %0, t; }" : "=r"(a) : "l"(p));
    return a;
}
__device__ __forceinline__ void cp16(unsigned sdst, const void* g) {
    asm volatile("cp.async.cg.shared.global [%0], [%1], 16;" :: "r"(sdst), "l"(g));
}
#define CP_COMMIT() asm volatile("cp.async.commit_group;" ::: "memory")
#define CP_WAIT1()  asm volatile("cp.async.wait_group 1;" ::: "memory")
#define CP_WAIT0()  asm volatile("cp.async.wait_group 0;" ::: "memory")

__device__ __forceinline__ void ldsm4(unsigned* r, unsigned addr) {
    asm volatile("ldmatrix.sync.aligned.m8n8.x4.shared.b16 {%0,%1,%2,%3}, [%4];"
                 : "=r"(r[0]), "=r"(r[1]), "=r"(r[2]), "=r"(r[3]) : "r"(addr));
}
__device__ __forceinline__ void mma16816(float* c, const unsigned* a, const unsigned* b) {
    asm volatile("mma.sync.aligned.m16n8k16.row.col.f32.bf16.bf16.f32 "
                 "{%0,%1,%2,%3}, {%4,%5,%6,%7}, {%8,%9}, {%0,%1,%2,%3};"
                 : "+f"(c[0]), "+f"(c[1]), "+f"(c[2]), "+f"(c[3])
                 : "r"(a[0]), "r"(a[1]), "r"(a[2]), "r"(a[3]), "r"(b[0]), "r"(b[1]));
}

__device__ __forceinline__ unsigned f2ord(float f) {
    unsigned u = __float_as_uint(f);
    return (u & 0x80000000u) ? ~u : (u | 0x80000000u);
}
__device__ __forceinline__ float decord(unsigned o) {
    unsigned u = (o & 0x80000000u) ? (o ^ 0x80000000u) : ~o;
    return __uint_as_float(u);
}
__device__ __forceinline__ void upd2(ull& a, ull& b, ull k) {
    if (k < a) { b = a; a = k; } else if (k < b) { b = k; }
}
__device__ __forceinline__ unsigned pack2(float a, float b) {
    __nv_bfloat162 p = __halves2bfloat162(__float2bfloat16_rn(a), __float2bfloat16_rn(b));
    return *reinterpret_cast<unsigned*>(&p);
}

// ---------------------------------------------------------------------------
// Kernel: fused codebook bf16 convert + row norms (one warp per cb row)
// ---------------------------------------------------------------------------
__global__ void vq_prep(const float* __restrict__ cb) {
    int w = (blockIdx.x * blockDim.x + threadIdx.x) >> 5;
    int lane = threadIdx.x & 31;
    if (w >= KK) return;
    const float4* src = (const float4*)(cb + (size_t)w * DD);
    float4 f0 = src[lane * 2], f1 = src[lane * 2 + 1];
    uint4 o;
    o.x = pack2(f0.x, f0.y); o.y = pack2(f0.z, f0.w);
    o.z = pack2(f1.x, f1.y); o.w = pack2(f1.z, f1.w);
    ((uint4*)(g_cb_hi + (size_t)w * DD))[lane] = o;
    float s = f0.x * f0.x + f0.y * f0.y + f0.z * f0.z + f0.w * f0.w
            + f1.x * f1.x + f1.y * f1.y + f1.z * f1.z + f1.w * f1.w;
#pragma unroll
    for (int off = 16; off; off >>= 1) s += __shfl_xor_sync(0xFFFFFFFFu, s, off);
    if (!lane) g_c2[w] = s;
}

// ---------------------------------------------------------------------------
// Main kernel: bf16 GEMM, 2 blocks/SM. grid = 256 blocks (64 queries each),
// 256 threads = 8 warps; warp (mg,nw): m32 rows x n32 cols per 64x128 tile.
// B streamed as 32KB k-half chunks (128 codes x 128 k), 2-buffer ring.
// ---------------------------------------------------------------------------
extern __shared__ char dsm[];

__device__ __forceinline__ float dot_exact(const float* a, const float* b) {
    float s0 = 0, s1 = 0, s2 = 0, s3 = 0;
    const float4* A = (const float4*)a;
    const float4* B = (const float4*)b;
#pragma unroll 16
    for (int i = 0; i < DD / 4; i++) {
        float4 u = A[i], w = B[i];
        s0 = fmaf(u.x, w.x, s0); s1 = fmaf(u.y, w.y, s1);
        s2 = fmaf(u.z, w.z, s2); s3 = fmaf(u.w, w.w, s3);
    }
    return (s0 + s1) + (s2 + s3);
}

__global__ void __launch_bounds__(NTHREADS, 2)
vq_main_mma(const float* __restrict__ x, const float* __restrict__ cb,
            float* __restrict__ out, int out_size) {
    const unsigned sb = smem_u32(dsm);
    const int tid = threadIdx.x;
    const int warp = tid >> 5, lane = tid & 31;
    const int mg = warp >> 2, nw = warp & 3;
    const int qbase = blockIdx.x * TM;

    // ---- B chunk load: 128 rows x 256B (k128), 16B-unit XOR swizzle ----
    auto issueB = [&](int c) {
        const int tile = c >> 1, kc = c & 1;
        const unsigned stage = sb + SM_BRING + (c & 1) * 32768;
        const __nv_bfloat16* src = g_cb_hi + (size_t)(tile * TN) * DD + kc * 128;
#pragma unroll
        for (int i = 0; i < 8; i++) {
            int l = tid + i * NTHREADS;             // 0..2047 16B units
            int row = l >> 4, u = l & 15;
            int su = (u & 8) | ((u ^ row) & 7);
            cp16(stage + row * 256 + su * 16, src + (size_t)row * DD + u * 8);
        }
    };

    // ---- phase 0: stage fp32 x tile (64KB = both ring buffers) ----
#pragma unroll
    for (int i = 0; i < 16; i++) {
        int l = tid + i * NTHREADS;                 // 0..4095 16B units
        int row = l >> 6, u = l & 63;
        cp16(sb + SM_BRING + row * 1024 + u * 16,
             x + (size_t)(qbase + row) * DD + u * 4);
    }
    CP_COMMIT();
    CP_WAIT0();
    __syncthreads();

    // ---- phase 1: convert x tile to bf16 swizzled A (quarter-row/thread) ----
    {
        const int row = tid >> 2, q = tid & 3;
        const float4* srcr = (const float4*)(dsm + SM_BRING + row * 1024 + q * 256);
#pragma unroll
        for (int j = 0; j < 8; j++) {
            float4 f0 = srcr[2 * j], f1 = srcr[2 * j + 1];
            uint4 w;
            w.x = pack2(f0.x, f0.y); w.y = pack2(f0.z, f0.w);
            w.z = pack2(f1.x, f1.y); w.w = pack2(f1.z, f1.w);
            int u = q * 8 + j;
            int su = (u & 24) | ((u ^ row) & 7);
            *(uint4*)(dsm + SM_A + row * 512 + su * 16) = w;
        }
    }
    __syncthreads();

    // ---- phase 2: main pipeline ----
    issueB(0);
    CP_COMMIT();

    const int a_rowp = (lane & 7) + ((lane >> 3) & 1) * 8;
    const int a_uoff = (lane >> 4) & 1;
    const int b_rowp = (lane & 7) + ((lane >> 4) & 1) * 8;
    const int b_uoff = (lane >> 3) & 1;

    float acc[2][4][4];
#pragma unroll
    for (int a = 0; a < 2; a++)
#pragma unroll
        for (int b = 0; b < 4; b++)
#pragma unroll
            for (int c = 0; c < 4; c++) acc[a][b][c] = 0.f;

    ull k1[4], k2[4];
    float thr2[4];
#pragma unroll
    for (int i = 0; i < 4; i++) { k1[i] = INFKEY; k2[i] = INFKEY; thr2[i] = 3.4e38f; }

#pragma unroll 1
    for (int c = 0; c < NCHUNKS; c++) {
        const int kc = c & 1;
        __syncthreads();                            // buffer (c+1)&1 consumed
        if (c + 1 < NCHUNKS) issueB(c + 1);
        CP_COMMIT();
        CP_WAIT1();                                 // chunk c landed
        __syncthreads();

        const unsigned stage = sb + SM_BRING + (c & 1) * 32768;
#pragma unroll
        for (int ks = 0; ks < 8; ks++) {            // k16 per step
            unsigned Bf[2][4];
#pragma unroll
            for (int nt = 0; nt < 2; nt++) {
                int rb = nw * 32 + nt * 16 + b_rowp;
                int u = 2 * ks + b_uoff;
                int su = (u & 8) | ((u ^ rb) & 7);
                ldsm4(Bf[nt], stage + rb * 256 + su * 16);
            }
#pragma unroll
            for (int mt = 0; mt < 2; mt++) {
                int ra = mg * 32 + mt * 16 + a_rowp;
                int ua = kc * 16 + 2 * ks + a_uoff;
                int su = (ua & 24) | ((ua ^ ra) & 7);
                unsigned Af[4];
                ldsm4(Af, sb + SM_A + ra * 512 + su * 16);
                mma16816(acc[mt][0], Af, &Bf[0][0]);
                mma16816(acc[mt][1], Af, &Bf[0][2]);
                mma16816(acc[mt][2], Af, &Bf[1][0]);
                mma16816(acc[mt][3], Af, &Bf[1][2]);
            }
        }

        if (kc == 1) {
            // ---- filtered epilogue for tile t = c>>1 (c2 via L2 ldg) ----
            const int t = c >> 1;
            float2 cc[4];
#pragma unroll
            for (int jj = 0; jj < 4; jj++)
                cc[jj] = __ldg((const float2*)(g_c2 + t * TN + nw * 32 + jj * 8 + 2 * (lane & 3)));
#pragma unroll
            for (int e = 0; e < 4; e++) {
                const int mt = e >> 1, rh = e & 1;
                float d[8];
#pragma unroll
                for (int jj = 0; jj < 4; jj++) {
                    d[2 * jj]     = fmaf(-2.f, acc[mt][jj][2 * rh],     cc[jj].x);
                    d[2 * jj + 1] = fmaf(-2.f, acc[mt][jj][2 * rh + 1], cc[jj].y);
                }
                float m = fminf(fminf(fminf(d[0], d[1]), fminf(d[2], d[3])),
                                fminf(fminf(d[4], d[5]), fminf(d[6], d[7])));
                if (m <= thr2[e]) {                 // rare: could enter best-2
#pragma unroll
                    for (int jj = 0; jj < 4; jj++) {
                        const int n0 = t * TN + nw * 32 + jj * 8 + 2 * (lane & 3);
                        upd2(k1[e], k2[e], ((ull)f2ord(d[2 * jj]) << 32) | (unsigned)n0);
                        upd2(k1[e], k2[e], ((ull)f2ord(d[2 * jj + 1]) << 32) | (unsigned)(n0 + 1));
                    }
                    thr2[e] = decord((unsigned)(k2[e] >> 32));
                }
#pragma unroll
                for (int jj = 0; jj < 4; jj++) {
                    acc[mt][jj][2 * rh] = 0.f;
                    acc[mt][jj][2 * rh + 1] = 0.f;
                }
            }
        }
    }

    // ---- merge best-2 across the 4 lanes sharing each row ----
#pragma unroll
    for (int i = 0; i < 4; i++) {
#pragma unroll
        for (int off = 1; off <= 2; off <<= 1) {
            ull o1 = __shfl_xor_sync(0xFFFFFFFFu, k1[i], off);
            ull o2 = __shfl_xor_sync(0xFFFFFFFFu, k2[i], off);
            ull m2 = (k2[i] < o2) ? k2[i] : o2;
            ull mx = (k1[i] > o1) ? k1[i] : o1;
            k1[i] = (k1[i] < o1) ? k1[i] : o1;
            k2[i] = (mx < m2) ? mx : m2;
        }
    }

    __syncthreads();                                // compute fully done
    ulonglong2* scr = (ulonglong2*)(dsm + SM_SCR);
    if ((lane & 3) == 0) {
#pragma unroll
        for (int s = 0; s < 4; s++) {
            int mt = s >> 1, rh = s & 1;
            int row = mg * 32 + mt * 16 + rh * 8 + (lane >> 2);
            scr[row * 4 + nw] = make_ulonglong2(k1[s], k2[s]);
        }
    }
    __syncthreads();

    // ---- per-query argmin (+ exact rescore), winners to smem ----
    unsigned* wins = (unsigned*)(dsm + SM_WIN);
    if (tid < TM) {
        const int row = tid;
        ull c8[8];
#pragma unroll
        for (int i = 0; i < 4; i++) {
            ulonglong2 v = scr[row * 4 + i];
            c8[2 * i] = v.x; c8[2 * i + 1] = v.y;
        }
        ull kmin = c8[0];
#pragma unroll
        for (int i = 1; i < 8; i++) kmin = (c8[i] < kmin) ? c8[i] : kmin;
        float dmin = decord((unsigned)(kmin >> 32));
        unsigned win = (unsigned)kmin;

        unsigned cand[8]; int nc = 0;
#pragma unroll
        for (int i = 0; i < 8; i++) {
            float d = decord((unsigned)(c8[i] >> 32));
            if (d - dmin < RESCORE_T) cand[nc++] = (unsigned)c8[i];
        }
        if (nc > 1) {
            const float* qv = x + (size_t)(qbase + row) * DD;
            float be = 3.4e38f; unsigned bi = 0xFFFFFFFFu;
            for (int j = 0; j < nc; j++) {
                unsigned i = cand[j];
                float e = fmaf(-2.f, dot_exact(qv, cb + (size_t)i * DD), g_c2[i]);
                if (e < be || (e == be && i < bi)) { be = e; bi = i; }
            }
            win = bi;
        }
        wins[row] = win;
        if (out_size >= 3 * QN * DD + QN)
            out[3 * QN * DD + qbase + row] = (float)win;
    }
    __syncthreads();

    // ---- fused output writes for this block's 64 rows ----
    {
        const int BND = QN * DD, BND4 = BND / 4;
        float4* o4 = (float4*)out;
#pragma unroll
        for (int i = 0; i < 16; i++) {
            int l = tid + i * NTHREADS;             // 0..4095 float4 units
            int row = l >> 6, c4 = l & 63;
            int g = qbase * 64 + l;                 // global float4 index
            unsigned idx = wins[row];
            float4 zq = ((const float4*)cb)[(size_t)idx * 64 + c4];
            float4 xv = ((const float4*)x)[g];
            if (out_size >= BND)     o4[g] = zq;            // x_recon
            if (out_size >= 2 * BND) o4[BND4 + g] = xv;     // z_e
            if (out_size >= 3 * BND) o4[2 * BND4 + g] = zq; // z_q
        }
    }
}

// ---------------------------------------------------------------------------
extern "C" void kernel_launch(void* const* d_in, const int* in_sizes, int n_in,
                              void* d_out, int out_size) {
    const float* x  = (const float*)d_in[0];
    const float* cb = (const float*)d_in[1];
    float* out = (float*)d_out;

    static int inited = 0;
    if (!inited) {
        cudaFuncSetAttribute(vq_main_mma, cudaFuncAttributeMaxDynamicSharedMemorySize,
                             SM_TOTAL);
        inited = 1;
    }

    vq_prep<<<KK * 32 / 256, 256>>>(cb);
    vq_main_mma<<<QN / TM, NTHREADS, SM_TOTAL>>>(x, cb, out, out_size);
}

// round 15
// speedup vs baseline: 1.2449x; 1.2449x over previous
#include <cuda_runtime.h>
#include <cuda_bf16.h>
#include <cstdint>

// ---------------------------------------------------------------------------
// Problem constants
// ---------------------------------------------------------------------------
#define QN 16384      // B*N queries
#define DD 256        // dim
#define KK 8192       // codebook size
#define TM 128        // queries per block
#define TN 128        // codes per tile
#define NTILES (KK / TN)          // 64
#define NCHUNKS (NTILES * 2)      // 128 k-half chunks per warp
#define NTHREADS 256
#define RESCORE_T 2.5f
#define INFKEY 0xFF800000FFFFFFFFull

// smem layout (bytes): A 64K | 8 warp rings x 16K = 128K | c2 32K = 224KB
#define SM_A 0
#define SM_BR 65536
#define SM_C2 196608
#define SM_TOTAL 229376
#define SM_SCR SM_BR              // merge scratch reuses ring area after loop

typedef unsigned long long ull;

// ---------------------------------------------------------------------------
// device scratch (static: no allocations allowed)
// ---------------------------------------------------------------------------
__device__ __nv_bfloat16 g_cb_hi[KK * DD];
__device__ float    g_c2[KK];
__device__ unsigned g_idx[QN];

// ---------------------------------------------------------------------------
// PTX helpers (sm_80-baseline: legal on plain sm_103 target)
// ---------------------------------------------------------------------------
__device__ __forceinline__ unsigned smem_u32(const void* p) {
    unsigned a;
    asm("{ .reg .u64 t; cvta.to.shared.u64 t, %1; cvt.u32.u64 %0, t; }" : "=r"(a) : "l"(p));
    return a;
}
__device__ __forceinline__ void cp16(unsigned sdst, const void* g) {
    asm volatile("cp.async.cg.shared.global [%0], [%1], 16;" :: "r"(sdst), "l"(g));
}
#define CP_COMMIT() asm volatile("cp.async.commit_group;" ::: "memory")
#define CP_WAIT0()  asm volatile("cp.async.wait_group 0;" ::: "memory")

__device__ __forceinline__ void ldsm4(unsigned* r, unsigned addr) {
    asm volatile("ldmatrix.sync.aligned.m8n8.x4.shared.b16 {%0,%1,%2,%3}, [%4];"
                 : "=r"(r[0]), "=r"(r[1]), "=r"(r[2]), "=r"(r[3]) : "r"(addr));
}
__device__ __forceinline__ void mma16816(float* c, const unsigned* a, const unsigned* b) {
    asm volatile("mma.sync.aligned.m16n8k16.row.col.f32.bf16.bf16.f32 "
                 "{%0,%1,%2,%3}, {%4,%5,%6,%7}, {%8,%9}, {%0,%1,%2,%3};"
                 : "+f"(c[0]), "+f"(c[1]), "+f"(c[2]), "+f"(c[3])
                 : "r"(a[0]), "r"(a[1]), "r"(a[2]), "r"(a[3]), "r"(b[0]), "r"(b[1]));
}

__device__ __forceinline__ unsigned f2ord(float f) {
    unsigned u = __float_as_uint(f);
    return (u & 0x80000000u) ? ~u : (u | 0x80000000u);
}
__device__ __forceinline__ float decord(unsigned o) {
    unsigned u = (o & 0x80000000u) ? (o ^ 0x80000000u) : ~o;
    return __uint_as_float(u);
}
__device__ __forceinline__ void upd2(ull& a, ull& b, ull k) {
    if (k < a) { b = a; a = k; } else if (k < b) { b = k; }
}
__device__ __forceinline__ unsigned pack2(float a, float b) {
    __nv_bfloat162 p = __halves2bfloat162(__float2bfloat16_rn(a), __float2bfloat16_rn(b));
    return *reinterpret_cast<unsigned*>(&p);
}

// ---------------------------------------------------------------------------
// Kernel: fused codebook bf16 convert + row norms (one warp per cb row)
// ---------------------------------------------------------------------------
__global__ void vq_prep(const float* __restrict__ cb) {
    int w = (blockIdx.x * blockDim.x + threadIdx.x) >> 5;
    int lane = threadIdx.x & 31;
    if (w >= KK) return;
    const float4* src = (const float4*)(cb + (size_t)w * DD);
    float4 f0 = src[lane * 2], f1 = src[lane * 2 + 1];
    uint4 o;
    o.x = pack2(f0.x, f0.y); o.y = pack2(f0.z, f0.w);
    o.z = pack2(f1.x, f1.y); o.w = pack2(f1.z, f1.w);
    ((uint4*)(g_cb_hi + (size_t)w * DD))[lane] = o;
    float s = f0.x * f0.x + f0.y * f0.y + f0.z * f0.z + f0.w * f0.w
            + f1.x * f1.x + f1.y * f1.y + f1.z * f1.z + f1.w * f1.w;
#pragma unroll
    for (int off = 16; off; off >>= 1) s += __shfl_xor_sync(0xFFFFFFFFu, s, off);
    if (!lane) g_c2[w] = s;
}

// ---------------------------------------------------------------------------
// Main kernel: warp-self-paced bf16 GEMM. grid = 128 blocks, 256 threads.
// Warp (mg,nw): m64 rows x n32 cols; private 2-stage B ring, own cp.async
// groups, NO block barriers in the 128-chunk mainloop.
// ---------------------------------------------------------------------------
extern __shared__ char dsm[];

__device__ __forceinline__ float dot_exact(const float* a, const float* b) {
    float s0 = 0, s1 = 0, s2 = 0, s3 = 0;
    const float4* A = (const float4*)a;
    const float4* B = (const float4*)b;
#pragma unroll 16
    for (int i = 0; i < DD / 4; i++) {
        float4 u = A[i], w = B[i];
        s0 = fmaf(u.x, w.x, s0); s1 = fmaf(u.y, w.y, s1);
        s2 = fmaf(u.z, w.z, s2); s3 = fmaf(u.w, w.w, s3);
    }
    return (s0 + s1) + (s2 + s3);
}

__global__ void __launch_bounds__(NTHREADS, 1)
vq_main_mma(const float* __restrict__ x, const float* __restrict__ cb) {
    const unsigned sb = smem_u32(dsm);
    const int tid = threadIdx.x;
    const int warp = tid >> 5, lane = tid & 31;
    const int mg = warp >> 2, nw = warp & 3;
    const int qbase = blockIdx.x * TM;

    // ---- per-warp B chunk load: 32 rows x 256B (k-half), XOR swizzle ----
    const unsigned ring = sb + SM_BR + warp * 16384;
    auto issueB = [&](int c) {
        const int t = c >> 1, kc = c & 1;
        const unsigned stage = ring + (c & 1) * 8192;
        const __nv_bfloat16* src =
            g_cb_hi + (size_t)(t * TN + nw * 32) * DD + kc * 128;
#pragma unroll
        for (int i = 0; i < 16; i++) {
            int l = lane + 32 * i;                  // 0..511 16B units
            int row = l >> 4, u = l & 15;
            int su = (u & 8) | ((u ^ row) & 7);
            cp16(stage + row * 256 + su * 16, src + (size_t)row * DD + u * 8);
        }
        CP_COMMIT();
    };

    // ---- phase 0: stage fp32 x tile (128KB = ring area) + c2 ----
#pragma unroll
    for (int i = 0; i < 32; i++) {
        int l = tid + i * NTHREADS;                 // 0..8191 16B units
        int row = l >> 6, u = l & 63;
        cp16(sb + SM_BR + row * 1024 + u * 16,
             x + (size_t)(qbase + row) * DD + u * 4);
    }
#pragma unroll
    for (int i = 0; i < 8; i++) {
        int l = i * NTHREADS + tid;                 // 0..2047
        cp16(sb + SM_C2 + l * 16, g_c2 + l * 4);
    }
    CP_COMMIT();
    CP_WAIT0();
    __syncthreads();

    // ---- phase 1: convert x tile to bf16 swizzled A ----
    {
        const int row = tid >> 1, half = tid & 1;
        const float4* srcr = (const float4*)(dsm + SM_BR + row * 1024 + half * 512);
#pragma unroll
        for (int j = 0; j < 16; j++) {
            float4 f0 = srcr[j * 2], f1 = srcr[j * 2 + 1];
            uint4 w;
            w.x = pack2(f0.x, f0.y); w.y = pack2(f0.z, f0.w);
            w.z = pack2(f1.x, f1.y); w.w = pack2(f1.z, f1.w);
            int u = half * 16 + j;
            int su = (u & 24) | ((u ^ row) & 7);
            *(uint4*)(dsm + SM_A + row * 512 + su * 16) = w;
        }
    }
    __syncthreads();                                // A visible to all warps

    // ---- phase 2: barrier-free self-paced mainloop ----
    const int a_rowp = (lane & 7) + ((lane >> 3) & 1) * 8;
    const int a_uoff = (lane >> 4) & 1;
    const int b_rowp = (lane & 7) + ((lane >> 4) & 1) * 8;
    const int b_uoff = (lane >> 3) & 1;
    const float* c2s = (const float*)(dsm + SM_C2);

    float acc[4][4][4];
#pragma unroll
    for (int a = 0; a < 4; a++)
#pragma unroll
        for (int b = 0; b < 4; b++)
#pragma unroll
            for (int c = 0; c < 4; c++) acc[a][b][c] = 0.f;

    ull k1[8], k2[8];
#pragma unroll
    for (int i = 0; i < 8; i++) { k1[i] = INFKEY; k2[i] = INFKEY; }

    issueB(0);

#pragma unroll 1
    for (int c = 0; c < NCHUNKS; c++) {
        CP_WAIT0();                                 // chunk c landed
        __syncwarp();
        if (c + 1 < NCHUNKS) issueB(c + 1);         // other buffer; overlaps compute

        const unsigned stage = ring + (c & 1) * 8192;
        const int kc = c & 1;
#pragma unroll
        for (int ks = 0; ks < 8; ks++) {            // k16 per step
            unsigned Bf[2][4];
#pragma unroll
            for (int nt = 0; nt < 2; nt++) {
                int rb = nt * 16 + b_rowp;
                int u = 2 * ks + b_uoff;
                int su = (u & 8) | ((u ^ rb) & 7);
                ldsm4(Bf[nt], stage + rb * 256 + su * 16);
            }
#pragma unroll
            for (int mt = 0; mt < 4; mt++) {
                int ra = mg * 64 + mt * 16 + a_rowp;
                int ua = kc * 16 + 2 * ks + a_uoff;
                int su = (ua & 24) | ((ua ^ ra) & 7);
                unsigned Af[4];
                ldsm4(Af, sb + SM_A + ra * 512 + su * 16);
                mma16816(acc[mt][0], Af, &Bf[0][0]);
                mma16816(acc[mt][1], Af, &Bf[0][2]);
                mma16816(acc[mt][2], Af, &Bf[1][0]);
                mma16816(acc[mt][3], Af, &Bf[1][2]);
            }
        }

        if (kc == 1) {
            // ---- per-tile epilogue (R4-proven) ----
            const int t = c >> 1;
#pragma unroll
            for (int mt = 0; mt < 4; mt++) {
#pragma unroll
                for (int jj = 0; jj < 4; jj++) {
                    const int n0 = t * TN + nw * 32 + jj * 8 + 2 * (lane & 3);
                    float2 cc = *(const float2*)(c2s + n0);
                    float d0 = fmaf(-2.f, acc[mt][jj][0], cc.x);
                    float d1 = fmaf(-2.f, acc[mt][jj][1], cc.y);
                    float d2 = fmaf(-2.f, acc[mt][jj][2], cc.x);
                    float d3 = fmaf(-2.f, acc[mt][jj][3], cc.y);
                    upd2(k1[2 * mt],     k2[2 * mt],     ((ull)f2ord(d0) << 32) | (unsigned)n0);
                    upd2(k1[2 * mt],     k2[2 * mt],     ((ull)f2ord(d1) << 32) | (unsigned)(n0 + 1));
                    upd2(k1[2 * mt + 1], k2[2 * mt + 1], ((ull)f2ord(d2) << 32) | (unsigned)n0);
                    upd2(k1[2 * mt + 1], k2[2 * mt + 1], ((ull)f2ord(d3) << 32) | (unsigned)(n0 + 1));
                    acc[mt][jj][0] = 0.f; acc[mt][jj][1] = 0.f;
                    acc[mt][jj][2] = 0.f; acc[mt][jj][3] = 0.f;
                }
            }
        }
    }

    // ---- merge best-2 across the 4 lanes sharing each row ----
#pragma unroll
    for (int i = 0; i < 8; i++) {
#pragma unroll
        for (int off = 1; off <= 2; off <<= 1) {
            ull o1 = __shfl_xor_sync(0xFFFFFFFFu, k1[i], off);
            ull o2 = __shfl_xor_sync(0xFFFFFFFFu, k2[i], off);
            ull m2 = (k2[i] < o2) ? k2[i] : o2;
            ull mx = (k1[i] > o1) ? k1[i] : o1;
            k1[i] = (k1[i] < o1) ? k1[i] : o1;
            k2[i] = (mx < m2) ? mx : m2;
        }
    }

    __syncthreads();                                // all warps done with rings
    ulonglong2* scr = (ulonglong2*)(dsm + SM_SCR);
    if ((lane & 3) == 0) {
#pragma unroll
        for (int s = 0; s < 8; s++) {
            int mt = s >> 1, rh = s & 1;
            int row = mg * 64 + mt * 16 + (lane >> 2) + rh * 8;
            scr[row * 4 + nw] = make_ulonglong2(k1[s], k2[s]);
        }
    }
    __syncthreads();

    // ---- final per-query: merge 4 slices (8 cands), rescore near-ties ----
    if (tid < TM) {
        const int row = tid;
        ull c8[8];
#pragma unroll
        for (int i = 0; i < 4; i++) {
            ulonglong2 v = scr[row * 4 + i];
            c8[2 * i] = v.x; c8[2 * i + 1] = v.y;
        }
        ull kmin = c8[0];
#pragma unroll
        for (int i = 1; i < 8; i++) kmin = (c8[i] < kmin) ? c8[i] : kmin;
        float dmin = decord((unsigned)(kmin >> 32));
        unsigned win = (unsigned)kmin;

        unsigned cand[8]; int nc = 0;
#pragma unroll
        for (int i = 0; i < 8; i++) {
            float d = decord((unsigned)(c8[i] >> 32));
            if (d - dmin < RESCORE_T) cand[nc++] = (unsigned)c8[i];
        }
        if (nc > 1) {
            const float* qv = x + (size_t)(qbase + row) * DD;
            float be = 3.4e38f; unsigned bi = 0xFFFFFFFFu;
            for (int j = 0; j < nc; j++) {
                unsigned i = cand[j];
                float e = fmaf(-2.f, dot_exact(qv, cb + (size_t)i * DD), c2s[i]);
                if (e < be || (e == be && i < bi)) { be = e; bi = i; }
            }
            win = bi;
        }
        g_idx[qbase + row] = win;
    }
}

// ---------------------------------------------------------------------------
// Output kernel: [x_recon | z_e | z_q | indices(float)]
// ---------------------------------------------------------------------------
__global__ void vq_out(const float* __restrict__ x, const float* __restrict__ cb,
                       float* __restrict__ out, int out_size) {
    const int BND = QN * DD, BND4 = BND / 4;
    int t = blockIdx.x * blockDim.x + threadIdx.x;
    if (t >= BND4) return;
    int q = t >> 6, c4 = t & 63;
    unsigned idx = g_idx[q];
    float4 zq = ((const float4*)cb)[(size_t)idx * (DD / 4) + c4];
    float4 xv = ((const float4*)x)[t];
    float4* o4 = (float4*)out;
    if (out_size >= BND)     o4[t] = zq;
    if (out_size >= 2 * BND) o4[BND4 + t] = xv;
    if (out_size >= 3 * BND) o4[2 * BND4 + t] = zq;
    if (c4 == 0 && out_size >= 3 * BND + QN) out[3 * BND + q] = (float)idx;
}

// ---------------------------------------------------------------------------
extern "C" void kernel_launch(void* const* d_in, const int* in_sizes, int n_in,
                              void* d_out, int out_size) {
    const float* x  = (const float*)d_in[0];
    const float* cb = (const float*)d_in[1];
    float* out = (float*)d_out;

    static int inited = 0;
    if (!inited) {
        cudaFuncSetAttribute(vq_main_mma, cudaFuncAttributeMaxDynamicSharedMemorySize,
                             SM_TOTAL);
        inited = 1;
    }

    vq_prep<<<KK * 32 / 256, 256>>>(cb);
    vq_main_mma<<<QN / TM, NTHREADS, SM_TOTAL>>>(x, cb);
    vq_out<<<(QN * DD / 4 + 255) / 256, 256>>>(x, cb, out, out_size);
}